// round 10
// baseline (speedup 1.0000x reference)
#include <cuda_runtime.h>
#include <cuda_fp16.h>
#include <cstdint>

// ---------------------------------------------------------------------------
// Scratch (__device__ globals — no allocations allowed)
// ---------------------------------------------------------------------------
static __device__ float  g_T[16 * 16 * 16 * 16 * 16];   //  4 MB  T[i][j][m][n][s]
static __device__ __half g_Wh[4096 * 4096];             // 32 MB  Wh[n=mno][k=ijk], fp16 x1024
static __device__ __half g_Xh[2048 * 4096];             // 16 MB  X fp16

#define W_SCALE   1024.0f
#define INV_SCALE 0.0009765625f

// ---------------------------------------------------------------------------
// Prep A (merged, independent halves):
//   blocks [0,256):    stage1  T[i,j,m,n,s] = sum_r first[i,r,m]*middle[j,r,s,n]
//   blocks [256,8448): convx   X float4 -> fp16
// ---------------------------------------------------------------------------
__global__ void mpo_prepA(const float* __restrict__ first,
                          const float* __restrict__ middle,
                          const float* __restrict__ x) {
    __shared__ float F[256];     // first[i][r][m]
    __shared__ float Md[4096];   // middle[j][r][s][n]
    const int t = threadIdx.x;
    if (blockIdx.x >= 256) {
        int id = (blockIdx.x - 256) * 256 + t;      // float4 index
        float4 v = ((const float4*)x)[id];
        __half2 lo = __floats2half2_rn(v.x, v.y);
        __half2 hi = __floats2half2_rn(v.z, v.w);
        uint2 p;
        p.x = *(uint32_t*)&lo;
        p.y = *(uint32_t*)&hi;
        ((uint2*)g_Xh)[id] = p;
        return;
    }
    const int i = blockIdx.x >> 4, j = blockIdx.x & 15;
    F[t] = first[i * 256 + t];
#pragma unroll
    for (int q = 0; q < 16; q++) Md[t + q * 256] = middle[j * 4096 + t + q * 256];
    __syncthreads();
#pragma unroll
    for (int q = 0; q < 16; q++) {
        int z = t + q * 256;                 // z = m*256 + n*16 + s
        int m = z >> 8, n = (z >> 4) & 15, s = z & 15;
        float acc = 0.f;
#pragma unroll
        for (int r = 0; r < 16; r++)
            acc += F[r * 16 + m] * Md[r * 256 + s * 16 + n];
        g_T[(i * 16 + j) * 4096 + z] = acc;
    }
}

// ---------------------------------------------------------------------------
// Stage 2 (o-split x4, proven round 9): block b -> (m=b>>6, n=(b>>2)&15, og=b&3)
// ---------------------------------------------------------------------------
__global__ void mpo_stage2(const float* __restrict__ last) {
    __shared__ float L[4096];    // last[k][s][o]
    const int t = threadIdx.x;
    const int m = blockIdx.x >> 6, n = (blockIdx.x >> 2) & 15, og = blockIdx.x & 3;
#pragma unroll
    for (int q = 0; q < 16; q++) L[t + q * 256] = last[t + q * 256];
    float Ts[16];
    const float* tp = g_T + (size_t)t * 4096 + m * 256 + n * 16;
#pragma unroll
    for (int s = 0; s < 16; s++) Ts[s] = tp[s];
    __syncthreads();
#pragma unroll
    for (int oo = 0; oo < 4; oo++) {
        const int o = og * 4 + oo;
        __half v[16];
#pragma unroll
        for (int k = 0; k < 16; k++) {
            float acc = 0.f;
#pragma unroll
            for (int s = 0; s < 16; s++) acc += Ts[s] * L[k * 256 + s * 16 + o];
            v[k] = __float2half_rn(acc * W_SCALE);
        }
        __half* wp = g_Wh + (size_t)(m * 256 + n * 16 + o) * 4096 + t * 16;
        *(uint4*)(wp)     = *(const uint4*)(v);
        *(uint4*)(wp + 8) = *(const uint4*)(v + 8);
    }
}

// ---------------------------------------------------------------------------
// GEMM: out(2048x4096) = (Xh @ Wh^T) * 2^-10 + bias
// Round-9 proven structure with ONE change: BK 32->64, stages 4->3
// (64 barriers instead of 128). 128 thr, 4 warps (64x64), 2 CTAs/SM.
// Smem per stage: A [128][72] halves + B [128][72] halves (row=18 4B-banks
// step -> 8-row ldmatrix phases hit 32 distinct banks, 16B-aligned rows).
// ---------------------------------------------------------------------------
#define HSTR 72
#define TILE_B (128 * HSTR * 2)        // 18432 B per operand tile
#define STG_B  (2 * TILE_B)            // 36864 B per stage
#define NSTAGE 3
#define SMEM_BYTES (NSTAGE * STG_B)    // 110592 B

__device__ __forceinline__ void cpa16(uint32_t saddr, const void* gaddr) {
    asm volatile("cp.async.cg.shared.global [%0], [%1], 16;"
                 :: "r"(saddr), "l"(gaddr));
}

__global__ void __launch_bounds__(128, 2)
mpo_gemm(const float* __restrict__ bias, float* __restrict__ out) {
    extern __shared__ char sm[];
    uint32_t smb;
    asm("{ .reg .u64 t; cvta.to.shared.u64 t, %1; cvt.u32.u64 %0, t; }"
        : "=r"(smb) : "l"(sm));
    const int tid  = threadIdx.x;
    const int lane = tid & 31, wid = tid >> 5;
    const int gid  = lane >> 2, tig = lane & 3;
    const int warpM = wid & 1, warpN = wid >> 1;   // 2M x 2N warps
    const int bM = blockIdx.y << 7;
    const int bN = blockIdx.x << 7;

    float acc[4][8][4];
#pragma unroll
    for (int mt = 0; mt < 4; mt++)
#pragma unroll
        for (int nt = 0; nt < 8; nt++)
#pragma unroll
            for (int q = 0; q < 4; q++) acc[mt][nt][q] = 0.f;

    // per k-tile (BK=64): A = 128 rows x 8 16B-chunks = 1024, B same;
    // 128 threads -> 8 A + 8 B chunks each
    auto issue = [&](int kt) {
        const uint32_t so = smb + (uint32_t)(kt % 3) * STG_B;
        const __half* gA = g_Xh + (size_t)bM * 4096 + kt * 64;
        const __half* gB = g_Wh + (size_t)bN * 4096 + kt * 64;
#pragma unroll
        for (int i = 0; i < 8; i++) {
            int z = tid + i * 128, r = z >> 3, c = z & 7;
            uint32_t off = (uint32_t)(r * HSTR + c * 8) * 2;
            cpa16(so + off, gA + (size_t)r * 4096 + c * 8);
            cpa16(so + TILE_B + off, gB + (size_t)r * 4096 + c * 8);
        }
    };

    issue(0); asm volatile("cp.async.commit_group;");
    issue(1); asm volatile("cp.async.commit_group;");

    const uint32_t aRow = warpM * 64 + (lane & 15);
    const uint32_t aKof = (lane >> 4) << 3;
    const uint32_t bRow = warpN * 64 + ((lane >> 4) << 3) + (lane & 7);
    const uint32_t bKof = ((lane >> 3) & 1) << 3;

    for (int kt = 0; kt < 64; kt++) {
        asm volatile("cp.async.wait_group 1;");
        __syncthreads();

        const uint32_t sA = smb + (uint32_t)(kt % 3) * STG_B;
        const uint32_t sB = sA + TILE_B;
#pragma unroll
        for (int ks = 0; ks < 4; ks++) {
            uint32_t a[4][4], b[8][2];
#pragma unroll
            for (int mt = 0; mt < 4; mt++) {
                uint32_t ad = sA + ((aRow + mt * 16) * HSTR + ks * 16 + aKof) * 2;
                asm volatile(
                    "ldmatrix.sync.aligned.m8n8.x4.shared.b16 {%0,%1,%2,%3}, [%4];"
                    : "=r"(a[mt][0]), "=r"(a[mt][1]), "=r"(a[mt][2]), "=r"(a[mt][3])
                    : "r"(ad));
            }
#pragma unroll
            for (int g = 0; g < 4; g++) {
                uint32_t bd = sB + ((bRow + g * 16) * HSTR + ks * 16 + bKof) * 2;
                asm volatile(
                    "ldmatrix.sync.aligned.m8n8.x4.shared.b16 {%0,%1,%2,%3}, [%4];"
                    : "=r"(b[2 * g][0]), "=r"(b[2 * g][1]),
                      "=r"(b[2 * g + 1][0]), "=r"(b[2 * g + 1][1])
                    : "r"(bd));
            }
#pragma unroll
            for (int mt = 0; mt < 4; mt++)
#pragma unroll
                for (int nt = 0; nt < 8; nt++) {
                    asm volatile(
                        "mma.sync.aligned.m16n8k16.row.col.f32.f16.f16.f32 "
                        "{%0,%1,%2,%3}, {%4,%5,%6,%7}, {%8,%9}, {%0,%1,%2,%3};\n"
                        : "+f"(acc[mt][nt][0]), "+f"(acc[mt][nt][1]),
                          "+f"(acc[mt][nt][2]), "+f"(acc[mt][nt][3])
                        : "r"(a[mt][0]), "r"(a[mt][1]), "r"(a[mt][2]), "r"(a[mt][3]),
                          "r"(b[nt][0]), "r"(b[nt][1]));
                }
        }

        if (kt + 2 < 64) issue(kt + 2);
        asm volatile("cp.async.commit_group;");
    }

    // epilogue: un-scale, + bias, float2 stores
#pragma unroll
    for (int mt = 0; mt < 4; mt++) {
        const int r = bM + warpM * 64 + mt * 16 + gid;
#pragma unroll
        for (int nt = 0; nt < 8; nt++) {
            const int c = bN + warpN * 64 + nt * 8 + tig * 2;
            const float2 bz = *(const float2*)(bias + c);
            float2 v0, v1;
            v0.x = acc[mt][nt][0] * INV_SCALE + bz.x;
            v0.y = acc[mt][nt][1] * INV_SCALE + bz.y;
            v1.x = acc[mt][nt][2] * INV_SCALE + bz.x;
            v1.y = acc[mt][nt][3] * INV_SCALE + bz.y;
            *(float2*)(out + (size_t)r * 4096 + c) = v0;
            *(float2*)(out + (size_t)(r + 8) * 4096 + c) = v1;
        }
    }
}

// ---------------------------------------------------------------------------
extern "C" void kernel_launch(void* const* d_in, const int* in_sizes, int n_in,
                              void* d_out, int out_size) {
    const float* x      = (const float*)d_in[0];
    const float* first  = (const float*)d_in[1];
    const float* middle = (const float*)d_in[2];
    const float* last   = (const float*)d_in[3];
    const float* bias   = (const float*)d_in[4];
    float* out = (float*)d_out;

    mpo_prepA<<<8448, 256>>>(first, middle, x);   // stage1 (256) + convx (8192)
    mpo_stage2<<<1024, 256>>>(last);

    cudaFuncSetAttribute(mpo_gemm, cudaFuncAttributeMaxDynamicSharedMemorySize,
                         SMEM_BYTES);
    dim3 gg(32, 16);   // 32 n-tiles x 16 m-tiles
    mpo_gemm<<<gg, 128, SMEM_BYTES>>>(bias, out);
}

// round 11
// speedup vs baseline: 1.1128x; 1.1128x over previous
#include <cuda_runtime.h>
#include <cuda_fp16.h>
#include <cstdint>

// ---------------------------------------------------------------------------
// Scratch (__device__ globals — no allocations allowed)
// ---------------------------------------------------------------------------
static __device__ float  g_T[16 * 16 * 16 * 16 * 16];   //  4 MB  T[i][j][m][n][s]
static __device__ __half g_Wh[4096 * 4096];             // 32 MB  Wh[n=mno][k=ijk], fp16 x1024
static __device__ __half g_Xh[2048 * 4096];             // 16 MB  X fp16

#define W_SCALE   1024.0f
#define INV_SCALE 0.0009765625f

// ---------------------------------------------------------------------------
// Prep A (merged, independent halves — proven round 10, 11.9us):
//   blocks [0,256):    stage1  T[i,j,m,n,s] = sum_r first[i,r,m]*middle[j,r,s,n]
//   blocks [256,8448): convx   X float4 -> fp16
// ---------------------------------------------------------------------------
__global__ void mpo_prepA(const float* __restrict__ first,
                          const float* __restrict__ middle,
                          const float* __restrict__ x) {
    __shared__ float F[256];     // first[i][r][m]
    __shared__ float Md[4096];   // middle[j][r][s][n]
    const int t = threadIdx.x;
    if (blockIdx.x >= 256) {
        int id = (blockIdx.x - 256) * 256 + t;      // float4 index
        float4 v = ((const float4*)x)[id];
        __half2 lo = __floats2half2_rn(v.x, v.y);
        __half2 hi = __floats2half2_rn(v.z, v.w);
        uint2 p;
        p.x = *(uint32_t*)&lo;
        p.y = *(uint32_t*)&hi;
        ((uint2*)g_Xh)[id] = p;
        return;
    }
    const int i = blockIdx.x >> 4, j = blockIdx.x & 15;
    F[t] = first[i * 256 + t];
#pragma unroll
    for (int q = 0; q < 16; q++) Md[t + q * 256] = middle[j * 4096 + t + q * 256];
    __syncthreads();
#pragma unroll
    for (int q = 0; q < 16; q++) {
        int z = t + q * 256;                 // z = m*256 + n*16 + s
        int m = z >> 8, n = (z >> 4) & 15, s = z & 15;
        float acc = 0.f;
#pragma unroll
        for (int r = 0; r < 16; r++)
            acc += F[r * 16 + m] * Md[r * 256 + s * 16 + n];
        g_T[(i * 16 + j) * 4096 + z] = acc;
    }
}

// ---------------------------------------------------------------------------
// Stage 2 (o-split x4, proven round 9): block b -> (m=b>>6, n=(b>>2)&15, og=b&3)
// ---------------------------------------------------------------------------
__global__ void mpo_stage2(const float* __restrict__ last) {
    __shared__ float L[4096];    // last[k][s][o]
    const int t = threadIdx.x;
    const int m = blockIdx.x >> 6, n = (blockIdx.x >> 2) & 15, og = blockIdx.x & 3;
#pragma unroll
    for (int q = 0; q < 16; q++) L[t + q * 256] = last[t + q * 256];
    float Ts[16];
    const float* tp = g_T + (size_t)t * 4096 + m * 256 + n * 16;
#pragma unroll
    for (int s = 0; s < 16; s++) Ts[s] = tp[s];
    __syncthreads();
#pragma unroll
    for (int oo = 0; oo < 4; oo++) {
        const int o = og * 4 + oo;
        __half v[16];
#pragma unroll
        for (int k = 0; k < 16; k++) {
            float acc = 0.f;
#pragma unroll
            for (int s = 0; s < 16; s++) acc += Ts[s] * L[k * 256 + s * 16 + o];
            v[k] = __float2half_rn(acc * W_SCALE);
        }
        __half* wp = g_Wh + (size_t)(m * 256 + n * 16 + o) * 4096 + t * 16;
        *(uint4*)(wp)     = *(const uint4*)(v);
        *(uint4*)(wp + 8) = *(const uint4*)(v + 8);
    }
}

// ---------------------------------------------------------------------------
// GEMM: out(2048x4096) = (Xh @ Wh^T) * 2^-10 + bias
// EXACT round-9 kernel (128 thr, 4 warps 64x64, 4-stage cp.async BK=32,
// HSTR 40, per-ks fragment loads, issue at END of loop body). 174.4us proven.
// ---------------------------------------------------------------------------
#define HSTR 40
#define TILE_B (128 * HSTR * 2)        // 10240 B per operand tile
#define STG_B  (2 * TILE_B)            // 20480 B per stage
#define NSTAGE 4
#define SMEM_BYTES (NSTAGE * STG_B)    // 81920 B

__device__ __forceinline__ void cpa16(uint32_t saddr, const void* gaddr) {
    asm volatile("cp.async.cg.shared.global [%0], [%1], 16;"
                 :: "r"(saddr), "l"(gaddr));
}

__global__ void __launch_bounds__(128, 2)
mpo_gemm(const float* __restrict__ bias, float* __restrict__ out) {
    extern __shared__ char sm[];
    uint32_t smb;
    asm("{ .reg .u64 t; cvta.to.shared.u64 t, %1; cvt.u32.u64 %0, t; }"
        : "=r"(smb) : "l"(sm));
    const int tid  = threadIdx.x;
    const int lane = tid & 31, wid = tid >> 5;
    const int gid  = lane >> 2, tig = lane & 3;
    const int warpM = wid & 1, warpN = wid >> 1;   // 2M x 2N warps
    const int bM = blockIdx.y << 7;
    const int bN = blockIdx.x << 7;

    float acc[4][8][4];
#pragma unroll
    for (int mt = 0; mt < 4; mt++)
#pragma unroll
        for (int nt = 0; nt < 8; nt++)
#pragma unroll
            for (int q = 0; q < 4; q++) acc[mt][nt][q] = 0.f;

    auto issue = [&](int kt) {
        const uint32_t so = smb + (uint32_t)(kt & 3) * STG_B;
        const __half* gA = g_Xh + (size_t)bM * 4096 + kt * 32;
        const __half* gB = g_Wh + (size_t)bN * 4096 + kt * 32;
#pragma unroll
        for (int i = 0; i < 4; i++) {
            int z = tid + i * 128, r = z >> 2, c = z & 3;
            uint32_t off = (uint32_t)(r * HSTR + c * 8) * 2;
            cpa16(so + off, gA + (size_t)r * 4096 + c * 8);
            cpa16(so + TILE_B + off, gB + (size_t)r * 4096 + c * 8);
        }
    };

    issue(0); asm volatile("cp.async.commit_group;");
    issue(1); asm volatile("cp.async.commit_group;");
    issue(2); asm volatile("cp.async.commit_group;");

    const uint32_t aRow = warpM * 64 + (lane & 15);
    const uint32_t aKof = (lane >> 4) << 3;
    const uint32_t bRow = warpN * 64 + ((lane >> 4) << 3) + (lane & 7);
    const uint32_t bKof = ((lane >> 3) & 1) << 3;

    for (int kt = 0; kt < 128; kt++) {
        asm volatile("cp.async.wait_group 2;");
        __syncthreads();

        const uint32_t sA = smb + (uint32_t)(kt & 3) * STG_B;
        const uint32_t sB = sA + TILE_B;
#pragma unroll
        for (int ks = 0; ks < 2; ks++) {
            uint32_t a[4][4], b[8][2];
#pragma unroll
            for (int mt = 0; mt < 4; mt++) {
                uint32_t ad = sA + ((aRow + mt * 16) * HSTR + ks * 16 + aKof) * 2;
                asm volatile(
                    "ldmatrix.sync.aligned.m8n8.x4.shared.b16 {%0,%1,%2,%3}, [%4];"
                    : "=r"(a[mt][0]), "=r"(a[mt][1]), "=r"(a[mt][2]), "=r"(a[mt][3])
                    : "r"(ad));
            }
#pragma unroll
            for (int g = 0; g < 4; g++) {
                uint32_t bd = sB + ((bRow + g * 16) * HSTR + ks * 16 + bKof) * 2;
                asm volatile(
                    "ldmatrix.sync.aligned.m8n8.x4.shared.b16 {%0,%1,%2,%3}, [%4];"
                    : "=r"(b[2 * g][0]), "=r"(b[2 * g][1]),
                      "=r"(b[2 * g + 1][0]), "=r"(b[2 * g + 1][1])
                    : "r"(bd));
            }
#pragma unroll
            for (int mt = 0; mt < 4; mt++)
#pragma unroll
                for (int nt = 0; nt < 8; nt++) {
                    asm volatile(
                        "mma.sync.aligned.m16n8k16.row.col.f32.f16.f16.f32 "
                        "{%0,%1,%2,%3}, {%4,%5,%6,%7}, {%8,%9}, {%0,%1,%2,%3};\n"
                        : "+f"(acc[mt][nt][0]), "+f"(acc[mt][nt][1]),
                          "+f"(acc[mt][nt][2]), "+f"(acc[mt][nt][3])
                        : "r"(a[mt][0]), "r"(a[mt][1]), "r"(a[mt][2]), "r"(a[mt][3]),
                          "r"(b[nt][0]), "r"(b[nt][1]));
                }
        }

        if (kt + 3 < 128) issue(kt + 3);
        asm volatile("cp.async.commit_group;");
    }

    // epilogue: un-scale, + bias, float2 stores
#pragma unroll
    for (int mt = 0; mt < 4; mt++) {
        const int r = bM + warpM * 64 + mt * 16 + gid;
#pragma unroll
        for (int nt = 0; nt < 8; nt++) {
            const int c = bN + warpN * 64 + nt * 8 + tig * 2;
            const float2 bz = *(const float2*)(bias + c);
            float2 v0, v1;
            v0.x = acc[mt][nt][0] * INV_SCALE + bz.x;
            v0.y = acc[mt][nt][1] * INV_SCALE + bz.y;
            v1.x = acc[mt][nt][2] * INV_SCALE + bz.x;
            v1.y = acc[mt][nt][3] * INV_SCALE + bz.y;
            *(float2*)(out + (size_t)r * 4096 + c) = v0;
            *(float2*)(out + (size_t)(r + 8) * 4096 + c) = v1;
        }
    }
}

// ---------------------------------------------------------------------------
extern "C" void kernel_launch(void* const* d_in, const int* in_sizes, int n_in,
                              void* d_out, int out_size) {
    const float* x      = (const float*)d_in[0];
    const float* first  = (const float*)d_in[1];
    const float* middle = (const float*)d_in[2];
    const float* last   = (const float*)d_in[3];
    const float* bias   = (const float*)d_in[4];
    float* out = (float*)d_out;

    mpo_prepA<<<8448, 256>>>(first, middle, x);   // stage1 (256) + convx (8192)
    mpo_stage2<<<1024, 256>>>(last);

    cudaFuncSetAttribute(mpo_gemm, cudaFuncAttributeMaxDynamicSharedMemorySize,
                         SMEM_BYTES);
    dim3 gg(32, 16);   // 32 n-tiles x 16 m-tiles
    mpo_gemm<<<gg, 128, SMEM_BYTES>>>(bias, out);
}